// round 1
// baseline (speedup 1.0000x reference)
#include <cuda_runtime.h>
#include <cstdint>

#define N0 900000
#define N1C 43008
#define N2C 2048
#define D 64
#define TWO_D 128

// ---------------- device-global scratch (no allocations allowed) ----------
__device__ float g_agg0[N1C * D];   // 11 MB  sum accumulator layer 0
__device__ float g_cnt0[N1C];       // in-degree counts layer 0
__device__ float g_h1[N1C * D];     // 11 MB  layer-0 output
__device__ float g_agg1[N2C * D];   // sum accumulator layer 1
__device__ float g_cnt1[N2C];

// ---------------- scatter: gather src row, red.add into dst row -----------
// one edge handled by 16 lanes, each lane one float4 (16B) -> 256B/row
__global__ void scatter_sum_kernel(const float* __restrict__ src_feat,
                                   const int* __restrict__ esrc,
                                   const int* __restrict__ edst,
                                   float* __restrict__ agg,
                                   float* __restrict__ cnt,
                                   int E) {
    int t = blockIdx.x * blockDim.x + threadIdx.x;
    int e = t >> 4;
    if (e >= E) return;
    int l = t & 15;
    int s = esrc[e];
    int d = edst[e];
    float4 v = reinterpret_cast<const float4*>(src_feat + (size_t)s * D)[l];
    float* dst = agg + (size_t)d * D + l * 4;
    asm volatile("red.global.add.v4.f32 [%0], {%1,%2,%3,%4};"
                 :: "l"(dst), "f"(v.x), "f"(v.y), "f"(v.z), "f"(v.w)
                 : "memory");
    if (l == 0) atomicAdd(cnt + d, 1.0f);
}

// ---------------- fused concat + mean + GEMM (+bias, optional relu) -------
// out[row, :] = act( [self[row], agg[row]/max(cnt,1)] @ w + b )
// block: 256 threads = 16 rows x 16 col-groups (4 cols each). 16 rows/block.
template <bool RELU>
__global__ void sage_gemm_kernel(const float* __restrict__ self_feat,
                                 const float* __restrict__ agg,
                                 const float* __restrict__ cnt,
                                 const float* __restrict__ w,   // [2D][D] row-major
                                 const float* __restrict__ b,   // [D]
                                 float* __restrict__ out,
                                 int n) {
    __shared__ float wsh[TWO_D * D];        // 32 KB
    __shared__ float insh[16][TWO_D + 1];   // 8.06 KB, padded
    __shared__ float scl[16];

    const int tid = threadIdx.x;
    const int tx = tid & 15;       // col group (4 cols)
    const int ty = tid >> 4;       // row within tile
    const int row0 = blockIdx.x * 16;

    // load weights
    #pragma unroll
    for (int i = tid; i < TWO_D * D; i += 256) wsh[i] = w[i];
    // per-row mean scale
    if (tid < 16) {
        int r = row0 + tid;
        float c = (r < n) ? cnt[r] : 1.0f;
        scl[tid] = 1.0f / fmaxf(c, 1.0f);
    }
    __syncthreads();

    // stage 16 concat rows into shared
    for (int i = tid; i < 16 * TWO_D; i += 256) {
        int r = i >> 7;
        int k = i & (TWO_D - 1);
        int row = row0 + r;
        float v = 0.0f;
        if (row < n) {
            v = (k < D) ? self_feat[(size_t)row * D + k]
                        : agg[(size_t)row * D + (k - D)] * scl[r];
        }
        insh[r][k] = v;
    }
    __syncthreads();

    float4 acc = *reinterpret_cast<const float4*>(b + tx * 4);
    const float* inrow = insh[ty];
    #pragma unroll
    for (int k = 0; k < TWO_D; k++) {
        float a = inrow[k];
        float4 wv = *reinterpret_cast<const float4*>(wsh + k * D + tx * 4);
        acc.x = fmaf(a, wv.x, acc.x);
        acc.y = fmaf(a, wv.y, acc.y);
        acc.z = fmaf(a, wv.z, acc.z);
        acc.w = fmaf(a, wv.w, acc.w);
    }
    if (RELU) {
        acc.x = fmaxf(acc.x, 0.0f);
        acc.y = fmaxf(acc.y, 0.0f);
        acc.z = fmaxf(acc.z, 0.0f);
        acc.w = fmaxf(acc.w, 0.0f);
    }
    int row = row0 + ty;
    if (row < n)
        *reinterpret_cast<float4*>(out + (size_t)row * D + tx * 4) = acc;
}

// ---------------- launch ---------------------------------------------------
extern "C" void kernel_launch(void* const* d_in, const int* in_sizes, int n_in,
                              void* d_out, int out_size) {
    const float* x          = (const float*)d_in[0];
    const float* w0         = (const float*)d_in[1];
    const float* b0         = (const float*)d_in[2];
    const float* w1         = (const float*)d_in[3];
    const float* b1         = (const float*)d_in[4];
    const int*   edge_src0  = (const int*)d_in[5];
    const int*   edge_dst0  = (const int*)d_in[6];
    const int*   edge_src1  = (const int*)d_in[7];
    const int*   edge_dst1  = (const int*)d_in[8];
    const int E0 = in_sizes[5];
    const int E1 = in_sizes[7];

    float *agg0, *cnt0, *h1, *agg1, *cnt1;
    cudaGetSymbolAddress((void**)&agg0, g_agg0);
    cudaGetSymbolAddress((void**)&cnt0, g_cnt0);
    cudaGetSymbolAddress((void**)&h1,   g_h1);
    cudaGetSymbolAddress((void**)&agg1, g_agg1);
    cudaGetSymbolAddress((void**)&cnt1, g_cnt1);

    // zero accumulators (graph-capturable memsets)
    cudaMemsetAsync(agg0, 0, (size_t)N1C * D * sizeof(float), 0);
    cudaMemsetAsync(cnt0, 0, (size_t)N1C * sizeof(float), 0);
    cudaMemsetAsync(agg1, 0, (size_t)N2C * D * sizeof(float), 0);
    cudaMemsetAsync(cnt1, 0, (size_t)N2C * sizeof(float), 0);

    // layer 0: scatter-mean over 860160 edges from x
    {
        int threads = E0 * 16;
        int grid = (threads + 255) / 256;
        scatter_sum_kernel<<<grid, 256>>>(x, edge_src0, edge_dst0, agg0, cnt0, E0);
    }
    // layer 0: concat-gemm + relu -> h1 [43008, 64]
    sage_gemm_kernel<true><<<N1C / 16, 256>>>(x, agg0, cnt0, w0, b0, h1, N1C);

    // layer 1: scatter-mean over 40960 edges from h1
    {
        int threads = E1 * 16;
        int grid = (threads + 255) / 256;
        scatter_sum_kernel<<<grid, 256>>>(h1, edge_src1, edge_dst1, agg1, cnt1, E1);
    }
    // layer 1: concat-gemm (no relu) -> d_out [2048, 64]
    sage_gemm_kernel<false><<<N2C / 16, 256>>>(h1, agg1, cnt1, w1, b1,
                                               (float*)d_out, N2C);
}